// round 16
// baseline (speedup 1.0000x reference)
#include <cuda_runtime.h>
#include <cstdint>
#include <cstdio>

#define Bn 2
#define Tn 2048
#define Cn 1024
#define Hn 16
#define Dn 64

// Scratch (no cudaMalloc allowed). All tensor values stored here are
// PRE-ROUNDED to tf32 (rna) so mma fragment loads need no cvt.
__device__ float g_Q[(size_t)Bn * Tn * Cn];
__device__ float g_K[(size_t)Bn * Tn * Cn];
__device__ float g_V[(size_t)Bn * Tn * Cn];
__device__ float g_Y[(size_t)Bn * Tn * Cn];
__device__ float g_X[(size_t)Bn * Tn * Cn];      // x rounded to tf32
__device__ float g_W[4 * (size_t)Cn * Cn];       // Wq,Wk,Wv,Wo rounded to tf32
__device__ float g_L[(size_t)Bn * Hn * Tn];      // softmax row sums (unnormalized)

// ---------- helpers ----------
__device__ __forceinline__ unsigned f2tf(float f) {
    unsigned u;
    asm("cvt.rna.tf32.f32 %0, %1;" : "=r"(u) : "f"(f));
    return u;
}
__device__ __forceinline__ float rtf(float f) { return __uint_as_float(f2tf(f)); }

__device__ __forceinline__ float fexp2(float x) {  // single MUFU.EX2
    float r;
    asm("ex2.approx.ftz.f32 %0, %1;" : "=f"(r) : "f"(x));
    return r;
}

__device__ __forceinline__ void mma_tf32(float c[4], const unsigned a[4], const unsigned b[2]) {
    asm volatile(
        "mma.sync.aligned.m16n8k8.row.col.f32.tf32.tf32.f32 "
        "{%0,%1,%2,%3},{%4,%5,%6,%7},{%8,%9},{%0,%1,%2,%3};"
        : "+f"(c[0]), "+f"(c[1]), "+f"(c[2]), "+f"(c[3])
        : "r"(a[0]), "r"(a[1]), "r"(a[2]), "r"(a[3]), "r"(b[0]), "r"(b[1]));
}

__device__ __forceinline__ void cp16(float* s, const float* g) {
    unsigned sa = (unsigned)__cvta_generic_to_shared(s);
    asm volatile("cp.async.cg.shared.global [%0], [%1], 16;" ::"r"(sa), "l"(g));
}

// =====================================================================
// Pre-round: x and the 4 weight matrices -> tf32-rounded copies.
// =====================================================================
__global__ __launch_bounds__(256) void round_kernel(
    const float4* __restrict__ x,  const float4* __restrict__ Wq,
    const float4* __restrict__ Wk, const float4* __restrict__ Wv,
    const float4* __restrict__ Wo)
{
    const int NX4 = (Bn * Tn * Cn) / 4;
    const int NW4 = (Cn * Cn) / 4;
    float4* gX = (float4*)g_X;
    float4* gW = (float4*)g_W;
    const int total = NX4 + 4 * NW4;
    for (int i = blockIdx.x * blockDim.x + threadIdx.x; i < total;
         i += gridDim.x * blockDim.x) {
        float4 v; float4* dst;
        if (i < NX4) { v = x[i]; dst = gX + i; }
        else {
            int j = i - NX4;
            int w = j / NW4, o = j - w * NW4;
            const float4* src = (w == 0) ? Wq : (w == 1) ? Wk : (w == 2) ? Wv : Wo;
            v = src[o]; dst = gW + j;
        }
        v.x = rtf(v.x); v.y = rtf(v.y); v.z = rtf(v.z); v.w = rtf(v.w);
        *dst = v;
    }
}

// =====================================================================
// Shared GEMM body: O[m,n] = sum_k A[m,k]*W[n,k] + bias[n], 128x128 tile.
// A, W pre-rounded tf32. roundo: round outputs (feed later mma stages).
// =====================================================================
__device__ __forceinline__ void proj_body(
    const float* __restrict__ A, const float* __restrict__ W,
    const float* __restrict__ bias, float* __restrict__ O,
    int bm, int bn, int roundo, float* sm)
{
    const int SA = 128 * 36;
    float* As = sm;
    float* Bs = sm + 2 * SA;

    const int tid  = threadIdx.x;
    const int warp = tid >> 5, lane = tid & 31;
    const int wm = warp >> 2, wn = warp & 3;
    const int g = lane >> 2, t4 = lane & 3;

    float acc[4][4][4];
#pragma unroll
    for (int i = 0; i < 4; i++)
#pragma unroll
        for (int j = 0; j < 4; j++)
#pragma unroll
            for (int k = 0; k < 4; k++) acc[i][j][k] = 0.f;

    auto load_tile = [&](int kt, int buf) {
        float* Ad = As + buf * SA;
        float* Bd = Bs + buf * SA;
#pragma unroll
        for (int j = 0; j < 4; j++) {
            int idx = tid + j * 256;
            int row = idx >> 3, c = (idx & 7) * 4;
            cp16(&Ad[row * 36 + c], &A[(size_t)(bm + row) * 1024 + kt + c]);
        }
#pragma unroll
        for (int j = 0; j < 4; j++) {
            int idx = tid + j * 256;
            int row = idx >> 3, c = (idx & 7) * 4;
            cp16(&Bd[row * 36 + c], &W[(size_t)(bn + row) * 1024 + kt + c]);
        }
        asm volatile("cp.async.commit_group;");
    };

    load_tile(0, 0);
    const int NT = 1024 / 32;
    for (int it = 0; it < NT; ++it) {
        if (it + 1 < NT) {
            load_tile((it + 1) * 32, (it + 1) & 1);
            asm volatile("cp.async.wait_group 1;");
        } else {
            asm volatile("cp.async.wait_group 0;");
        }
        __syncthreads();
        const float* Ab = As + (it & 1) * SA;
        const float* Bb = Bs + (it & 1) * SA;
#pragma unroll
        for (int kk = 0; kk < 4; kk++) {
            unsigned af[4][4], bf[4][2];
            const int kc = kk * 8 + t4;
#pragma unroll
            for (int mt = 0; mt < 4; mt++) {
                int r = wm * 64 + mt * 16 + g;
                af[mt][0] = __float_as_uint(Ab[r * 36 + kc]);
                af[mt][1] = __float_as_uint(Ab[(r + 8) * 36 + kc]);
                af[mt][2] = __float_as_uint(Ab[r * 36 + kc + 4]);
                af[mt][3] = __float_as_uint(Ab[(r + 8) * 36 + kc + 4]);
            }
#pragma unroll
            for (int nt = 0; nt < 4; nt++) {
                int cidx = wn * 32 + nt * 8 + g;
                bf[nt][0] = __float_as_uint(Bb[cidx * 36 + kc]);
                bf[nt][1] = __float_as_uint(Bb[cidx * 36 + kc + 4]);
            }
#pragma unroll
            for (int mt = 0; mt < 4; mt++)
#pragma unroll
                for (int nt = 0; nt < 4; nt++) mma_tf32(acc[mt][nt], af[mt], bf[nt]);
        }
        __syncthreads();
    }

#pragma unroll
    for (int mt = 0; mt < 4; mt++) {
        int r = bm + wm * 64 + mt * 16 + g;
#pragma unroll
        for (int nt = 0; nt < 4; nt++) {
            int c = bn + wn * 32 + nt * 8 + t4 * 2;
            float bv0 = bias[c], bv1 = bias[c + 1];
            float o0 = acc[mt][nt][0] + bv0, o1 = acc[mt][nt][1] + bv1;
            float o2 = acc[mt][nt][2] + bv0, o3 = acc[mt][nt][3] + bv1;
            if (roundo) { o0 = rtf(o0); o1 = rtf(o1); o2 = rtf(o2); o3 = rtf(o3); }
            *(float2*)&O[(size_t)r * 1024 + c]       = make_float2(o0, o1);
            *(float2*)&O[(size_t)(r + 8) * 1024 + c] = make_float2(o2, o3);
        }
    }
}

__global__ __launch_bounds__(256) void proj_kernel(
    const float* __restrict__ A,
    const float* __restrict__ W0, const float* __restrict__ W1, const float* __restrict__ W2,
    const float* __restrict__ b0p, const float* __restrict__ b1p, const float* __restrict__ b2p,
    float* __restrict__ O0, float* __restrict__ O1, float* __restrict__ O2,
    int roundo)
{
    const int z = blockIdx.z;
    const float* W    = (z == 0) ? W0  : ((z == 1) ? W1  : W2);
    const float* bias = (z == 0) ? b0p : ((z == 1) ? b1p : b2p);
    float*       O    = (z == 0) ? O0  : ((z == 1) ? O1  : O2);
    extern __shared__ float sm[];
    proj_body(A, W, bias, O, blockIdx.y * 128, blockIdx.x * 128, roundo, sm);
}

// =====================================================================
// Single-pass attention. One block per (b,h,128-row q tile).
// 64-key chunks, cp.async double-buffered K/V, P via register shuffles.
// Stores UNNORMALIZED exp scores to att (st.cs) + row sums to g_L;
// Y is normalized in-kernel. smem ~104KB -> 2 CTAs/SM.
// =====================================================================
__global__ __launch_bounds__(256, 2) void attn_kernel(float* __restrict__ att)
{
    const int qt = (int)gridDim.x - 1 - (int)blockIdx.x;  // heavy tiles first
    const int bh = blockIdx.y;
    const int b  = bh >> 4;
    const int q0 = qt * 128;

    extern __shared__ float sm[];
    float* Qs = sm;                   // [128][68]
    float* Ks = sm + 128 * 68;        // [2][64][68]
    float* Vs = Ks + 2 * 64 * 68;     // [2][64][72]

    const int tid  = threadIdx.x;
    const int warp = tid >> 5, lane = tid & 31;
    const int g = lane >> 2, t4 = lane & 3;
    const size_t base = ((size_t)b * Tn) * Cn + (size_t)(bh & 15) * Dn;

    const int nch = 2 * (qt + 1);          // 64-key chunks

    auto load_kv = [&](int ch, int buf) {
        float* Kd = Ks + buf * (64 * 68);
        float* Vd = Vs + buf * (64 * 72);
        const int kc = ch * 64;
#pragma unroll
        for (int j = 0; j < 4; j++) {
            int idx = tid + j * 256;
            int row = idx >> 4, c = (idx & 15) * 4;
            cp16(&Kd[row * 68 + c], &g_K[base + (size_t)(kc + row) * Cn + c]);
        }
#pragma unroll
        for (int j = 0; j < 4; j++) {
            int idx = tid + j * 256;
            int row = idx >> 4, c = (idx & 15) * 4;
            cp16(&Vd[row * 72 + c], &g_V[base + (size_t)(kc + row) * Cn + c]);
        }
        asm volatile("cp.async.commit_group;");
    };

    // Prologue: Q tile + chunk 0 (one cp.async group)
#pragma unroll
    for (int j = 0; j < 8; j++) {
        int idx = tid + j * 256;
        int row = idx >> 4, c = (idx & 15) * 4;
        cp16(&Qs[row * 68 + c], &g_Q[base + (size_t)(q0 + row) * Cn + c]);
    }
    load_kv(0, 0);

    const int r0 = q0 + warp * 16 + g;   // this thread's two rows
    const int r1 = r0 + 8;
    const int rl = warp * 16 + g;
    const float SCL = 0.125f * 1.44269504088896f;  // (1/sqrt(D)) * log2(e)

    float l0 = 0.f, l1 = 0.f;
    float yacc[8][4];
#pragma unroll
    for (int nt = 0; nt < 8; nt++)
#pragma unroll
        for (int k = 0; k < 4; k++) yacc[nt][k] = 0.f;

    for (int ch = 0; ch < nch; ++ch) {
        if (ch + 1 < nch) {
            load_kv(ch + 1, (ch + 1) & 1);
            asm volatile("cp.async.wait_group 1;");
        } else {
            asm volatile("cp.async.wait_group 0;");
        }
        __syncthreads();

        const float* Kb = Ks + (ch & 1) * (64 * 68);
        const float* Vb = Vs + (ch & 1) * (64 * 72);
        const int kc = ch * 64;

        // ---- scores: S[16 rows x 64 keys] per warp ----
        float sacc[8][4];
#pragma unroll
        for (int nt = 0; nt < 8; nt++)
#pragma unroll
            for (int k = 0; k < 4; k++) sacc[nt][k] = 0.f;
#pragma unroll
        for (int kk = 0; kk < 8; kk++) {
            unsigned af[4];
            const int kd = kk * 8 + t4;
            af[0] = __float_as_uint(Qs[rl * 68 + kd]);
            af[1] = __float_as_uint(Qs[(rl + 8) * 68 + kd]);
            af[2] = __float_as_uint(Qs[rl * 68 + kd + 4]);
            af[3] = __float_as_uint(Qs[(rl + 8) * 68 + kd + 4]);
#pragma unroll
            for (int nt = 0; nt < 8; nt++) {
                unsigned bf[2];
                bf[0] = __float_as_uint(Kb[(nt * 8 + g) * 68 + kd]);
                bf[1] = __float_as_uint(Kb[(nt * 8 + g) * 68 + kd + 4]);
                mma_tf32(sacc[nt], af, bf);
            }
        }

        // ---- exp (unnormalized), mask, store att, accumulate l ----
        const bool diag = (ch >= 2 * qt);
#pragma unroll
        for (int nt = 0; nt < 8; nt++) {
            int colk = nt * 8 + t4 * 2;
            int key  = kc + colk;
            float p00 = fexp2(sacc[nt][0] * SCL);
            float p01 = fexp2(sacc[nt][1] * SCL);
            float p10 = fexp2(sacc[nt][2] * SCL);
            float p11 = fexp2(sacc[nt][3] * SCL);
            if (diag) {
                if (key     > r0) p00 = 0.f;
                if (key + 1 > r0) p01 = 0.f;
                if (key     > r1) p10 = 0.f;
                if (key + 1 > r1) p11 = 0.f;
            }
            l0 += p00 + p01;
            l1 += p10 + p11;
            __stcs((float2*)&att[((size_t)bh * Tn + r0) * Tn + key], make_float2(p00, p01));
            __stcs((float2*)&att[((size_t)bh * Tn + r1) * Tn + key], make_float2(p10, p11));
            // tf32-rounded for the PV mma
            sacc[nt][0] = rtf(p00); sacc[nt][1] = rtf(p01);
            sacc[nt][2] = rtf(p10); sacc[nt][3] = rtf(p11);
        }

        // ---- Y += P @ V : A-fragments of P via register shuffles ----
        const int src0 = (lane & 28) | (t4 >> 1);
#pragma unroll
        for (int kk = 0; kk < 8; kk++) {
            float v00 = __shfl_sync(0xffffffffu, sacc[kk][0], src0);
            float v01 = __shfl_sync(0xffffffffu, sacc[kk][1], src0);
            float v02 = __shfl_sync(0xffffffffu, sacc[kk][2], src0);
            float v03 = __shfl_sync(0xffffffffu, sacc[kk][3], src0);
            float v10 = __shfl_sync(0xffffffffu, sacc[kk][0], src0 + 2);
            float v11 = __shfl_sync(0xffffffffu, sacc[kk][1], src0 + 2);
            float v12 = __shfl_sync(0xffffffffu, sacc[kk][2], src0 + 2);
            float v13 = __shfl_sync(0xffffffffu, sacc[kk][3], src0 + 2);
            const bool odd = (t4 & 1);
            unsigned af[4];
            af[0] = __float_as_uint(odd ? v01 : v00);  // P[g,    kk*8+t4]
            af[1] = __float_as_uint(odd ? v03 : v02);  // P[g+8,  kk*8+t4]
            af[2] = __float_as_uint(odd ? v11 : v10);  // P[g,    kk*8+t4+4]
            af[3] = __float_as_uint(odd ? v13 : v12);  // P[g+8,  kk*8+t4+4]
            const int kx = kk * 8 + t4;
#pragma unroll
            for (int nt = 0; nt < 8; nt++) {
                unsigned bf[2];
                bf[0] = __float_as_uint(Vb[kx * 72 + nt * 8 + g]);
                bf[1] = __float_as_uint(Vb[(kx + 4) * 72 + nt * 8 + g]);
                mma_tf32(yacc[nt], af, bf);
            }
        }
        __syncthreads();
    }

    // row sums -> all quad lanes, store g_L, normalize Y
    l0 += __shfl_xor_sync(0xffffffffu, l0, 1);
    l0 += __shfl_xor_sync(0xffffffffu, l0, 2);
    l1 += __shfl_xor_sync(0xffffffffu, l1, 1);
    l1 += __shfl_xor_sync(0xffffffffu, l1, 2);
    if (t4 == 0) {
        g_L[(size_t)bh * Tn + r0] = l0;
        g_L[(size_t)bh * Tn + r1] = l1;
    }
    const float inv0 = 1.f / l0, inv1 = 1.f / l1;

#pragma unroll
    for (int nt = 0; nt < 8; nt++) {
        int c = nt * 8 + t4 * 2;
        *(float2*)&g_Y[base + (size_t)(q0 + rl) * Cn + c] =
            make_float2(rtf(yacc[nt][0] * inv0), rtf(yacc[nt][1] * inv0));
        *(float2*)&g_Y[base + (size_t)(q0 + rl + 8) * Cn + c] =
            make_float2(rtf(yacc[nt][2] * inv1), rtf(yacc[nt][3] * inv1));
    }
}

// =====================================================================
// Tail: block-specialized fusion of O-projection GEMM (blocks [0,256))
// and att normalization + upper-triangle zero-fill (blocks [256, 16640)).
// The GEMM is tensor-bound, normalization is memory-bound -> they overlap.
// =====================================================================
#define GEMM_BLKS 256
__global__ __launch_bounds__(256) void tail_kernel(
    const float* __restrict__ A, const float* __restrict__ W,
    const float* __restrict__ bias, float* __restrict__ O,
    float* __restrict__ att)
{
    if (blockIdx.x < GEMM_BLKS) {
        extern __shared__ float sm[];
        int gx = blockIdx.x;
        proj_body(A, W, bias, O, (gx >> 3) * 128, (gx & 7) * 128, 0, sm);
        return;
    }
    // normalization: 4 rows per block
    const int nb  = blockIdx.x - GEMM_BLKS;
    const int tid = threadIdx.x;
    const float4 z4 = make_float4(0.f, 0.f, 0.f, 0.f);
#pragma unroll
    for (int i = 0; i < 4; i++) {
        const int r = nb * 4 + i;                 // global row in [0, 65536)
        const int t = r & (Tn - 1);               // position within sequence
        const float inv = 1.f / g_L[r];
        float* rowp = att + (size_t)r * Tn;
#pragma unroll
        for (int k = 0; k < 2; k++) {
            int c = tid * 4 + k * 1024;
            if (c > t) {
                __stcs((float4*)&rowp[c], z4);    // pure zero, no read
            } else {
                float4 v = __ldcs((const float4*)&rowp[c]);
                v.x *= inv;
                v.y = (c + 1 <= t) ? v.y * inv : 0.f;
                v.z = (c + 2 <= t) ? v.z * inv : 0.f;
                v.w = (c + 3 <= t) ? v.w * inv : 0.f;
                __stcs((float4*)&rowp[c], v);
            }
        }
    }
}

// =====================================================================
extern "C" void kernel_launch(void* const* d_in, const int* in_sizes, int n_in,
                              void* d_out, int out_size)
{
    const float* x  = (const float*)d_in[0];
    const float* Wq = (const float*)d_in[1];
    const float* bq = (const float*)d_in[2];
    const float* Wk = (const float*)d_in[3];
    const float* bk = (const float*)d_in[4];
    const float* Wv = (const float*)d_in[5];
    const float* bv = (const float*)d_in[6];
    const float* Wo = (const float*)d_in[7];
    const float* bo = (const float*)d_in[8];

    float* y   = (float*)d_out;
    float* att = y + (size_t)Bn * Tn * Cn;

    float *pQ, *pK, *pV, *pY, *pX, *pW;
    cudaGetSymbolAddress((void**)&pQ, g_Q);
    cudaGetSymbolAddress((void**)&pK, g_K);
    cudaGetSymbolAddress((void**)&pV, g_V);
    cudaGetSymbolAddress((void**)&pY, g_Y);
    cudaGetSymbolAddress((void**)&pX, g_X);
    cudaGetSymbolAddress((void**)&pW, g_W);
    const size_t NW = (size_t)Cn * Cn;

    const int PROJ_SMEM = 4 * 128 * 36 * 4;                         // 73728 B
    const int ATTN_SMEM = (128 * 68 + 2 * 64 * 68 + 2 * 64 * 72) * 4;  // 106496 B
    cudaFuncSetAttribute(proj_kernel, cudaFuncAttributeMaxDynamicSharedMemorySize, PROJ_SMEM);
    cudaFuncSetAttribute(attn_kernel, cudaFuncAttributeMaxDynamicSharedMemorySize, ATTN_SMEM);
    cudaFuncSetAttribute(tail_kernel, cudaFuncAttributeMaxDynamicSharedMemorySize, PROJ_SMEM);

    // 0) round x + weights to tf32 once
    round_kernel<<<8192, 256>>>((const float4*)x, (const float4*)Wq, (const float4*)Wk,
                                (const float4*)Wv, (const float4*)Wo);
    // 1) QKV projections (one launch, z selects weight/bias/output); outputs rounded
    proj_kernel<<<dim3(8, 32, 3), 256, PROJ_SMEM>>>(pX, pW, pW + NW, pW + 2 * NW,
                                                    bq, bk, bv, pQ, pK, pV, 1);
    // 2) single-pass attention: unnormalized att + g_L + normalized Y
    attn_kernel<<<dim3(Tn / 128, Bn * Hn), 256, ATTN_SMEM>>>(att);
    // 3) fused: O-projection GEMM + att normalization/zero-fill
    tail_kernel<<<GEMM_BLKS + (Bn * Hn * Tn) / 4, 256, PROJ_SMEM>>>(
        pY, pW + 3 * NW, bo, y, att);
}